// round 8
// baseline (speedup 1.0000x reference)
#include <cuda_runtime.h>
#include <cuda_fp16.h>
#include <cstdint>

// ============================================================================
// UniversalKANLinear: out[b,o] = sum_k (softplus(x[b,k])-ln2) * W[o,k]
//                              + (softplus(1)-ln2) * W[o,2048]
// B=8192, K=2048, N=2048.
// R8: ONE mega-kernel. Low block IDs do prep (W->fp16, phi(x)->fp16, bias,
//     zero split regions); high block IDs run the fp16 mma.sync GEMM and
//     spin on release/acquire counters until their inputs are ready.
//     Same launch shape for all blocks => co-residency => no deadlock;
//     prep overlaps the GEMM ramp instead of serializing in front of it.
//     Counters self-reset via a done-counter => graph-replay safe.
// ============================================================================

#define BATCH_M 8192
#define DIM_K   2048
#define DIM_N   2048
#define W_COLS  2049

#define BM 128
#define BN 128
#define BK 64
#define KITERS (DIM_K / BK)     // 32
#define STAGES 3
#define KHALF (KITERS / 2)      // 16

#define MTILES (BATCH_M / BM)   // 64
#define NTILES (DIM_N / BN)     // 16
#define NTILES_TOTAL (MTILES * NTILES)            // 1024
#define FULL_TILES 888
#define SPLIT_TILES (NTILES_TOTAL - FULL_TILES)   // 136
#define GEMM_BLOCKS (FULL_TILES + 2 * SPLIT_TILES) // 1160

#define NW_BLK 1024   // W prep: 2 o-rows per block
#define NX_BLK 1024   // x prep: 8 rows per block
#define NZ_BLK (SPLIT_TILES * 2)                  // 272 (half tile each)
#define NPREP (NW_BLK + NX_BLK + NZ_BLK)          // 2320
#define TOTAL_BLOCKS (NPREP + GEMM_BLOCKS)        // 3480

// smem: rows of 64 fp16 = 128 B, XOR-swizzled in 16B chunks
#define A_STAGE_BYTES (BM * 128)
#define B_STAGE_BYTES (BN * 128)
#define STAGE_BYTES   (A_STAGE_BYTES + B_STAGE_BYTES)  // 32768
#define SMEM_BYTES    (STAGES * STAGE_BYTES)           // 98304

#define C_BIAS 0.62011450695827751f   // softplus(1) - ln2
#define LN2F   0.69314718055994531f

// ---------------- scratch (device globals: allocation-free rule) -----------
__device__ __align__(1024) __half g_A[(size_t)BATCH_M * DIM_K];  // 32 MB phi(x)
__device__ __align__(1024) __half g_B[(size_t)DIM_N * DIM_K];    // 8 MB W
__device__ __align__(128)  float  g_bias[DIM_N];

// progress counters (self-resetting each launch via g_done)
__device__ unsigned g_cntW;       // -> NW_BLK
__device__ unsigned g_cntA[64];   // per 128-row block of A -> 16
__device__ unsigned g_cntZ;       // -> NZ_BLK
__device__ unsigned g_done;       // -> TOTAL_BLOCKS, last block resets all

// ---------------- helpers ---------------------------------------------------
__device__ __forceinline__ uint32_t smem_u32(const void* p) {
    uint32_t a;
    asm("{ .reg .u64 t; cvta.to.shared.u64 t, %1; cvt.u32.u64 %0, t; }" : "=r"(a) : "l"(p));
    return a;
}

#define CP_ASYNC16(dst_u32, src_ptr) \
    asm volatile("cp.async.cg.shared.global [%0], [%1], 16;" \
                 :: "r"(dst_u32), "l"(src_ptr) : "memory")
#define CP_COMMIT() asm volatile("cp.async.commit_group;" ::: "memory")
#define CP_WAIT(N)  asm volatile("cp.async.wait_group %0;" :: "n"(N) : "memory")

#define LDMATRIX_X4(r0, r1, r2, r3, addr) \
    asm volatile("ldmatrix.sync.aligned.m8n8.x4.shared.b16 {%0,%1,%2,%3}, [%4];" \
                 : "=r"(r0), "=r"(r1), "=r"(r2), "=r"(r3) : "r"(addr))

#define MMA_F16(c, a0, a1, a2, a3, b0, b1) \
    asm volatile("mma.sync.aligned.m16n8k16.row.col.f32.f16.f16.f32 " \
                 "{%0,%1,%2,%3}, {%4,%5,%6,%7}, {%8,%9}, {%0,%1,%2,%3};" \
                 : "+f"((c)[0]), "+f"((c)[1]), "+f"((c)[2]), "+f"((c)[3]) \
                 : "r"(a0), "r"(a1), "r"(a2), "r"(a3), "r"(b0), "r"(b1))

__device__ __forceinline__ float phi_f(float x) {
    float t = __expf(-fabsf(x));
    return fmaxf(x, 0.0f) + __logf(1.0f + t) - LN2F;
}

__device__ __forceinline__ uint2 phi_pack(float4 v) {
    __half2 h0 = __floats2half2_rn(phi_f(v.x), phi_f(v.y));
    __half2 h1 = __floats2half2_rn(phi_f(v.z), phi_f(v.w));
    uint2 p;
    p.x = *reinterpret_cast<uint32_t*>(&h0);
    p.y = *reinterpret_cast<uint32_t*>(&h1);
    return p;
}

// ---------------- the mega kernel -------------------------------------------
__global__ void __launch_bounds__(256, 2)
kan_mega_kernel(const float* __restrict__ x, const float* __restrict__ W,
                float* __restrict__ out) {
    extern __shared__ char smem[];
    const int bid = blockIdx.x;
    const int tid = threadIdx.x;

    if (bid < NW_BLK) {
        // ================= W prep: 2 o-rows -> g_B fp16 + bias ==============
        const int row = bid * 2 + (tid >> 7);
        const int l128 = tid & 127;
        const float* wr = W + (size_t)row * W_COLS;
        __half* dst = g_B + (size_t)row * DIM_K;
        float v[16];
        #pragma unroll
        for (int j = 0; j < 16; j++) v[j] = wr[j * 128 + l128];
        #pragma unroll
        for (int j = 0; j < 16; j++) dst[j * 128 + l128] = __float2half_rn(v[j]);
        if (l128 == 0) g_bias[row] = C_BIAS * wr[DIM_K];
        __syncthreads();
        if (tid == 0) { __threadfence(); atomicAdd(&g_cntW, 1u); }
    } else if (bid < NW_BLK + NX_BLK) {
        // ================= x prep: 8 rows, phi -> g_A fp16 ==================
        const int xb = bid - NW_BLK;
        const int row = xb * 8 + (tid >> 5);
        const int lane = tid & 31;
        const float4* src = reinterpret_cast<const float4*>(x) + (size_t)row * 512 + lane;
        uint2* dst = reinterpret_cast<uint2*>(g_A) + (size_t)row * 512 + lane;
        #pragma unroll
        for (int b4 = 0; b4 < 4; b4++) {
            float4 v[4];
            #pragma unroll
            for (int jj = 0; jj < 4; jj++) v[jj] = src[(b4 * 4 + jj) * 32];
            #pragma unroll
            for (int jj = 0; jj < 4; jj++) dst[(b4 * 4 + jj) * 32] = phi_pack(v[jj]);
        }
        __syncthreads();
        if (tid == 0) { __threadfence(); atomicAdd(&g_cntA[xb >> 4], 1u); }
    } else if (bid < NPREP) {
        // ================= zero split-tile out regions ======================
        const int zb = bid - (NW_BLK + NX_BLK);
        const int t = FULL_TILES + (zb >> 1);
        const int mx = t >> 4, ny = t & 15;
        const int half = zb & 1;
        float4 z = {0.f, 0.f, 0.f, 0.f};
        #pragma unroll
        for (int i = 0; i < 8; i++) {
            int inner = i * 256 + tid;               // 0..2047 float4s
            int mrow = mx * BM + half * 64 + (inner >> 5);
            int c4 = inner & 31;
            *reinterpret_cast<float4*>(out + (size_t)mrow * DIM_N + ny * BN + c4 * 4) = z;
        }
        __syncthreads();
        if (tid == 0) { __threadfence(); atomicAdd(&g_cntZ, 1u); }
    } else {
        // ================= GEMM =============================================
        const uint32_t sbase = smem_u32(smem);
        const int lane = tid & 31;
        const int wid = tid >> 5;
        const int wm = wid & 1;
        const int wn = wid >> 1;
        const int r = lane >> 2;
        const int c = lane & 3;

        // tile scheduling: full tiles, then split-K halves of the tail
        const int gb = bid - NPREP;
        int tile, k0, kn, khalf = 0;
        bool split;
        if (gb < FULL_TILES) {
            tile = gb; k0 = 0; kn = KITERS; split = false;
        } else {
            int u = gb - FULL_TILES;
            tile = FULL_TILES + (u % SPLIT_TILES);
            khalf = u / SPLIT_TILES;
            k0 = khalf * KHALF; kn = KHALF; split = true;
        }
        const int mx = tile >> 4;                 // ascending with bid
        const int m0 = mx * BM;
        const int n0 = (tile & 15) * BN;

        // wait for W fully converted + our A row-block
        if (tid == 0) {
            while (atomicAdd(&g_cntW, 0u) < (unsigned)NW_BLK) __nanosleep(128);
            while (atomicAdd(&g_cntA[mx], 0u) < 16u) __nanosleep(128);
            __threadfence();
        }
        __syncthreads();

        auto copy_stage = [&](int s, int kt) {
            const uint32_t sA = sbase + (uint32_t)s * STAGE_BYTES;
            const uint32_t sB = sA + A_STAGE_BYTES;
            const __half* gA = g_A + (size_t)m0 * DIM_K + (size_t)kt * BK;
            const __half* gB = g_B + (size_t)n0 * DIM_K + (size_t)kt * BK;
            #pragma unroll
            for (int i = 0; i < 4; i++) {
                int v = tid + i * 256;
                int row = v >> 3, c16 = v & 7;
                CP_ASYNC16(sA + row * 128 + ((c16 ^ (row & 7)) * 16),
                           gA + (size_t)row * DIM_K + c16 * 8);
            }
            #pragma unroll
            for (int i = 0; i < 4; i++) {
                int v = tid + i * 256;
                int row = v >> 3, c16 = v & 7;
                CP_ASYNC16(sB + row * 128 + ((c16 ^ (row & 7)) * 16),
                           gB + (size_t)row * DIM_K + c16 * 8);
            }
        };

        float acc[4][4][4];
        #pragma unroll
        for (int mt = 0; mt < 4; mt++)
            #pragma unroll
            for (int nt = 0; nt < 4; nt++)
                #pragma unroll
                for (int i = 0; i < 4; i++) acc[mt][nt][i] = 0.0f;

        copy_stage(0, k0); CP_COMMIT();
        copy_stage(1, k0 + 1); CP_COMMIT();

        const int a_row = (lane & 15);
        const int a_ch  = (lane >> 4);
        const int b_nrow = ((lane >> 4) << 3) + (lane & 7);
        const int b_ch  = (lane >> 3) & 1;

        int rs = 0;
        for (int kt = 0; kt < kn; kt++) {
            CP_WAIT(1);
            __syncthreads();
            if (kt + 2 < kn) copy_stage((kt + 2) % STAGES, k0 + kt + 2);
            CP_COMMIT();

            const uint32_t sA = sbase + (uint32_t)rs * STAGE_BYTES + (wm * 64) * 128;
            const uint32_t sB = sbase + (uint32_t)rs * STAGE_BYTES + A_STAGE_BYTES
                                + (wn * 32) * 128;

            #pragma unroll
            for (int ks = 0; ks < 4; ks++) {
                uint32_t a[4][4], b[2][4];
                #pragma unroll
                for (int mt = 0; mt < 4; mt++) {
                    int row = mt * 16 + a_row;
                    int ch = ks * 2 + a_ch;
                    uint32_t addr = sA + row * 128 + ((ch ^ (row & 7)) * 16);
                    LDMATRIX_X4(a[mt][0], a[mt][1], a[mt][2], a[mt][3], addr);
                }
                #pragma unroll
                for (int np = 0; np < 2; np++) {
                    int row = np * 16 + b_nrow;
                    int ch = ks * 2 + b_ch;
                    uint32_t addr = sB + row * 128 + ((ch ^ (row & 7)) * 16);
                    LDMATRIX_X4(b[np][0], b[np][1], b[np][2], b[np][3], addr);
                }
                #pragma unroll
                for (int mt = 0; mt < 4; mt++) {
                    #pragma unroll
                    for (int np = 0; np < 2; np++) {
                        MMA_F16(acc[mt][2 * np],     a[mt][0], a[mt][1], a[mt][2], a[mt][3],
                                b[np][0], b[np][1]);
                        MMA_F16(acc[mt][2 * np + 1], a[mt][0], a[mt][1], a[mt][2], a[mt][3],
                                b[np][2], b[np][3]);
                    }
                }
            }
            if (++rs == STAGES) rs = 0;
        }

        // split tiles: their out region must be zeroed before atomics
        if (split) {
            if (tid == 0) {
                while (atomicAdd(&g_cntZ, 0u) < (unsigned)NZ_BLK) __nanosleep(128);
                __threadfence();
            }
            __syncthreads();
        }

        // epilogue
        const int mbase = m0 + wm * 64;
        const int nbase = n0 + wn * 32;
        const bool addb = !split || (khalf == 0);
        #pragma unroll
        for (int mt = 0; mt < 4; mt++) {
            #pragma unroll
            for (int nt = 0; nt < 4; nt++) {
                int mrow = mbase + mt * 16 + r;
                int ncol = nbase + nt * 8 + 2 * c;
                float2 bv = *reinterpret_cast<const float2*>(g_bias + ncol);
                float v0x = acc[mt][nt][0] + (addb ? bv.x : 0.0f);
                float v0y = acc[mt][nt][1] + (addb ? bv.y : 0.0f);
                float v1x = acc[mt][nt][2] + (addb ? bv.x : 0.0f);
                float v1y = acc[mt][nt][3] + (addb ? bv.y : 0.0f);
                float* p0 = out + (size_t)mrow * DIM_N + ncol;
                float* p1 = out + (size_t)(mrow + 8) * DIM_N + ncol;
                if (!split) {
                    *reinterpret_cast<float2*>(p0) = make_float2(v0x, v0y);
                    *reinterpret_cast<float2*>(p1) = make_float2(v1x, v1y);
                } else {
                    atomicAdd(p0, v0x);
                    atomicAdd(p0 + 1, v0y);
                    atomicAdd(p1, v1x);
                    atomicAdd(p1 + 1, v1y);
                }
            }
        }
    }

    // ---- common tail: done-count + self-reset of counters for next replay ----
    __syncthreads();
    if (tid == 0) {
        __threadfence();
        unsigned d = atomicAdd(&g_done, 1u);
        if (d == (unsigned)(TOTAL_BLOCKS - 1)) {
            g_cntW = 0u;
            g_cntZ = 0u;
            #pragma unroll
            for (int i = 0; i < 64; i++) g_cntA[i] = 0u;
            __threadfence();
            g_done = 0u;
        }
    }
}

// ---------------- host launch ----------------------------------------------
extern "C" void kernel_launch(void* const* d_in, const int* in_sizes, int n_in,
                              void* d_out, int out_size) {
    const float* x = (const float*)d_in[0];
    const float* W = (const float*)d_in[1];
    float* out = (float*)d_out;

    cudaFuncSetAttribute(kan_mega_kernel, cudaFuncAttributeMaxDynamicSharedMemorySize,
                         SMEM_BYTES);

    kan_mega_kernel<<<TOTAL_BLOCKS, 256, SMEM_BYTES>>>(x, W, out);
}